// round 1
// baseline (speedup 1.0000x reference)
#include <cuda_runtime.h>
#include <math.h>

#define DMODEL 1024
#define NHEAD  16
#define HD     64
#define NB     4
#define SQ     1024
#define SK     2048

// Scratch (allocation-free rule: __device__ globals)
__device__ float g_Q[NB * SQ * DMODEL];   // 16 MB, q_lin after RoPE, [B,S,H*D]
__device__ float g_K[NB * SK * DMODEL];   // 32 MB
__device__ float g_V[NB * SK * DMODEL];   // 32 MB
__device__ float g_O[NB * SQ * DMODEL];   // 16 MB, attention output [B,S,H*D]

// ---------------------------------------------------------------------------
// C[M,N] = A[M,K] @ W[N,K]^T + bias[N]   (torch Linear). All dims mult of 128/16.
// 128x128 tile, BK=16, 256 threads, 8x8 microtile.
// ---------------------------------------------------------------------------
__global__ __launch_bounds__(256, 2)
void gemm_nt_bias(const float* __restrict__ A, const float* __restrict__ W,
                  const float* __restrict__ bias, float* __restrict__ C,
                  int M, int N, int K)
{
    __shared__ float As[16][132];
    __shared__ float Bs[16][132];
    const int tid = threadIdx.x;
    const int tx = tid & 15;
    const int ty = tid >> 4;
    const int m0 = blockIdx.y * 128;
    const int n0 = blockIdx.x * 128;

    float acc[8][8];
#pragma unroll
    for (int i = 0; i < 8; i++)
#pragma unroll
        for (int j = 0; j < 8; j++) acc[i][j] = 0.f;

    const int lrow = tid >> 2;        // 0..63 (plus +64 on second pass)
    const int lk   = (tid & 3) * 4;   // 0,4,8,12

    for (int k0 = 0; k0 < K; k0 += 16) {
#pragma unroll
        for (int l = 0; l < 2; l++) {
            int row = lrow + l * 64;
            float4 a = *(const float4*)&A[(m0 + row) * K + k0 + lk];
            As[lk + 0][row] = a.x; As[lk + 1][row] = a.y;
            As[lk + 2][row] = a.z; As[lk + 3][row] = a.w;
            float4 w = *(const float4*)&W[(n0 + row) * K + k0 + lk];
            Bs[lk + 0][row] = w.x; Bs[lk + 1][row] = w.y;
            Bs[lk + 2][row] = w.z; Bs[lk + 3][row] = w.w;
        }
        __syncthreads();
#pragma unroll
        for (int kk = 0; kk < 16; kk++) {
            float af[8], bf[8];
#pragma unroll
            for (int i = 0; i < 8; i += 4) {
                float4 t = *(const float4*)&As[kk][ty * 8 + i];
                af[i] = t.x; af[i + 1] = t.y; af[i + 2] = t.z; af[i + 3] = t.w;
                float4 u = *(const float4*)&Bs[kk][tx * 8 + i];
                bf[i] = u.x; bf[i + 1] = u.y; bf[i + 2] = u.z; bf[i + 3] = u.w;
            }
#pragma unroll
            for (int i = 0; i < 8; i++)
#pragma unroll
                for (int j = 0; j < 8; j++)
                    acc[i][j] = fmaf(af[i], bf[j], acc[i][j]);
        }
        __syncthreads();
    }

#pragma unroll
    for (int i = 0; i < 8; i++) {
        int m = m0 + ty * 8 + i;
#pragma unroll
        for (int j = 0; j < 8; j += 4) {
            int n = n0 + tx * 8 + j;
            float4 o;
            o.x = acc[i][j + 0] + bias[n + 0];
            o.y = acc[i][j + 1] + bias[n + 1];
            o.z = acc[i][j + 2] + bias[n + 2];
            o.w = acc[i][j + 3] + bias[n + 3];
            *(float4*)&C[m * N + n] = o;
        }
    }
}

// ---------------------------------------------------------------------------
// In-place RoPE over [rows, DMODEL]: per head pair (d, d+32), angle = pos * f_d
// pos = (row % L) * posStride. Mirrors the fp32 JAX pipeline.
// One block per row, 512 threads = 16 heads x 32 pairs.
// ---------------------------------------------------------------------------
__global__ void rope_kernel(float* __restrict__ X, int L, int posStride)
{
    int row = blockIdx.x;
    int t = threadIdx.x;
    int h = t >> 5;
    int j = t & 31;
    float pos = (float)((row % L) * posStride);
    float inv = 1.0f / powf(10000.0f, (float)j * (1.0f / 32.0f));
    float ang = pos * inv;
    float s, c;
    sincosf(ang, &s, &c);
    float* p = X + (size_t)row * DMODEL + h * HD + j;
    float x1 = p[0];
    float x2 = p[32];
    p[0]  = x1 * c - x2 * s;
    p[32] = x2 * c + x1 * s;
}

// ---------------------------------------------------------------------------
// Flash attention: block = (64-query tile, head, batch). Online softmax over
// K=2048 in 64-wide chunks. Smem arrays stride 65 => conflict-free scalar LDS.
// Thread microtile 4 rows x 4 cols (16x16 thread grid).
// ---------------------------------------------------------------------------
#define AST 65
#define ATTN_SMEM (4 * 64 * AST * 4)   // Qt, Kt, Vs, Ps

__global__ __launch_bounds__(256)
void attn_kernel(const float* __restrict__ Q, const float* __restrict__ Km,
                 const float* __restrict__ Vm, float* __restrict__ Oo)
{
    extern __shared__ float sm[];
    float* Qt = sm;                  // [d=64][r=64] stride AST, pre-scaled by 1/8
    float* Kt = Qt + 64 * AST;       // [d=64][c=64]
    float* Vs = Kt + 64 * AST;       // [k=64][d=64]
    float* Ps = Vs + 64 * AST;       // [r=64][c=64]

    const int tid = threadIdx.x;
    const int tx = tid & 15;
    const int ty = tid >> 4;
    const int s0 = blockIdx.x * 64;
    const int h  = blockIdx.y;
    const int b  = blockIdx.z;

    // Load+transpose Q tile (scaled by softmax scale 1/sqrt(64) = 0.125)
    {
        const float* src = Q + (size_t)(b * SQ + s0) * DMODEL + h * HD;
#pragma unroll
        for (int u = 0; u < 4; u++) {
            int e = tid + u * 256;          // 0..1023
            int r = e >> 4;
            int d4 = (e & 15) << 2;
            float4 v = *(const float4*)&src[r * DMODEL + d4];
            Qt[(d4 + 0) * AST + r] = v.x * 0.125f;
            Qt[(d4 + 1) * AST + r] = v.y * 0.125f;
            Qt[(d4 + 2) * AST + r] = v.z * 0.125f;
            Qt[(d4 + 3) * AST + r] = v.w * 0.125f;
        }
    }

    float m_i[4], l_i[4], oacc[4][4];
#pragma unroll
    for (int i = 0; i < 4; i++) {
        m_i[i] = -INFINITY;
        l_i[i] = 0.f;
#pragma unroll
        for (int j = 0; j < 4; j++) oacc[i][j] = 0.f;
    }

    const float* ksrc = Km + (size_t)(b * SK) * DMODEL + h * HD;
    const float* vsrc = Vm + (size_t)(b * SK) * DMODEL + h * HD;

    for (int c0 = 0; c0 < SK; c0 += 64) {
        // Load K chunk (transposed) and V chunk (natural)
#pragma unroll
        for (int u = 0; u < 4; u++) {
            int e = tid + u * 256;
            int r = e >> 4;
            int d4 = (e & 15) << 2;
            float4 kv4 = *(const float4*)&ksrc[(c0 + r) * DMODEL + d4];
            Kt[(d4 + 0) * AST + r] = kv4.x;
            Kt[(d4 + 1) * AST + r] = kv4.y;
            Kt[(d4 + 2) * AST + r] = kv4.z;
            Kt[(d4 + 3) * AST + r] = kv4.w;
            float4 vv4 = *(const float4*)&vsrc[(c0 + r) * DMODEL + d4];
            Vs[r * AST + d4 + 0] = vv4.x;
            Vs[r * AST + d4 + 1] = vv4.y;
            Vs[r * AST + d4 + 2] = vv4.z;
            Vs[r * AST + d4 + 3] = vv4.w;
        }
        __syncthreads();   // (A) tiles ready

        // S = Q K^T   (rows ty*4.., cols tx*4..)
        float sc[4][4];
#pragma unroll
        for (int i = 0; i < 4; i++)
#pragma unroll
            for (int j = 0; j < 4; j++) sc[i][j] = 0.f;

#pragma unroll 4
        for (int d = 0; d < 64; d++) {
            float q0 = Qt[d * AST + ty * 4 + 0];
            float q1 = Qt[d * AST + ty * 4 + 1];
            float q2 = Qt[d * AST + ty * 4 + 2];
            float q3 = Qt[d * AST + ty * 4 + 3];
            float k0 = Kt[d * AST + tx * 4 + 0];
            float k1 = Kt[d * AST + tx * 4 + 1];
            float k2 = Kt[d * AST + tx * 4 + 2];
            float k3 = Kt[d * AST + tx * 4 + 3];
            sc[0][0] = fmaf(q0, k0, sc[0][0]); sc[0][1] = fmaf(q0, k1, sc[0][1]);
            sc[0][2] = fmaf(q0, k2, sc[0][2]); sc[0][3] = fmaf(q0, k3, sc[0][3]);
            sc[1][0] = fmaf(q1, k0, sc[1][0]); sc[1][1] = fmaf(q1, k1, sc[1][1]);
            sc[1][2] = fmaf(q1, k2, sc[1][2]); sc[1][3] = fmaf(q1, k3, sc[1][3]);
            sc[2][0] = fmaf(q2, k0, sc[2][0]); sc[2][1] = fmaf(q2, k1, sc[2][1]);
            sc[2][2] = fmaf(q2, k2, sc[2][2]); sc[2][3] = fmaf(q2, k3, sc[2][3]);
            sc[3][0] = fmaf(q3, k0, sc[3][0]); sc[3][1] = fmaf(q3, k1, sc[3][1]);
            sc[3][2] = fmaf(q3, k2, sc[3][2]); sc[3][3] = fmaf(q3, k3, sc[3][3]);
        }

        // Online softmax (row groups = 16 consecutive lanes; shuffle-reduce)
#pragma unroll
        for (int i = 0; i < 4; i++) {
            float mx = fmaxf(fmaxf(sc[i][0], sc[i][1]), fmaxf(sc[i][2], sc[i][3]));
#pragma unroll
            for (int off = 8; off >= 1; off >>= 1)
                mx = fmaxf(mx, __shfl_xor_sync(0xffffffffu, mx, off));
            float mnew = fmaxf(m_i[i], mx);
            float ssum = 0.f;
#pragma unroll
            for (int j = 0; j < 4; j++) {
                float p = expf(sc[i][j] - mnew);
                sc[i][j] = p;
                ssum += p;
            }
#pragma unroll
            for (int off = 8; off >= 1; off >>= 1)
                ssum += __shfl_xor_sync(0xffffffffu, ssum, off);
            float alpha = expf(m_i[i] - mnew);
            l_i[i] = l_i[i] * alpha + ssum;
            m_i[i] = mnew;
#pragma unroll
            for (int j = 0; j < 4; j++) {
                oacc[i][j] *= alpha;
                Ps[(ty * 4 + i) * AST + tx * 4 + j] = sc[i][j];
            }
        }
        __syncthreads();   // (B) Ps ready

        // O += P @ V   (o cols are head-dim cols tx*4..)
#pragma unroll 4
        for (int k = 0; k < 64; k++) {
            float p0 = Ps[(ty * 4 + 0) * AST + k];
            float p1 = Ps[(ty * 4 + 1) * AST + k];
            float p2 = Ps[(ty * 4 + 2) * AST + k];
            float p3 = Ps[(ty * 4 + 3) * AST + k];
#pragma unroll
            for (int j = 0; j < 4; j++) {
                float v = Vs[k * AST + tx * 4 + j];
                oacc[0][j] = fmaf(p0, v, oacc[0][j]);
                oacc[1][j] = fmaf(p1, v, oacc[1][j]);
                oacc[2][j] = fmaf(p2, v, oacc[2][j]);
                oacc[3][j] = fmaf(p3, v, oacc[3][j]);
            }
        }
        __syncthreads();   // (C) safe to overwrite tiles next chunk
    }

    // Normalize and store [B,S,H*D]
#pragma unroll
    for (int i = 0; i < 4; i++) {
        float invl = 1.0f / l_i[i];
        int r = s0 + ty * 4 + i;
        float4 o4 = make_float4(oacc[i][0] * invl, oacc[i][1] * invl,
                                oacc[i][2] * invl, oacc[i][3] * invl);
        *(float4*)&Oo[(size_t)(b * SQ + r) * DMODEL + h * HD + tx * 4] = o4;
    }
}

// ---------------------------------------------------------------------------
extern "C" void kernel_launch(void* const* d_in, const int* in_sizes, int n_in,
                              void* d_out, int out_size)
{
    const float* query = (const float*)d_in[0];
    const float* kv    = (const float*)d_in[1];
    const float* q_w   = (const float*)d_in[2];
    const float* q_b   = (const float*)d_in[3];
    const float* k_w   = (const float*)d_in[4];
    const float* k_b   = (const float*)d_in[5];
    const float* v_w   = (const float*)d_in[6];
    const float* v_b   = (const float*)d_in[7];
    const float* out_w = (const float*)d_in[8];
    const float* out_b = (const float*)d_in[9];
    float* out = (float*)d_out;

    float *Qb, *Kb, *Vb, *Ob;
    cudaGetSymbolAddress((void**)&Qb, g_Q);
    cudaGetSymbolAddress((void**)&Kb, g_K);
    cudaGetSymbolAddress((void**)&Vb, g_V);
    cudaGetSymbolAddress((void**)&Ob, g_O);

    // Projections (+bias)
    gemm_nt_bias<<<dim3(8, 32), 256>>>(query, q_w, q_b, Qb, NB * SQ, DMODEL, DMODEL);
    gemm_nt_bias<<<dim3(8, 64), 256>>>(kv,    k_w, k_b, Kb, NB * SK, DMODEL, DMODEL);
    gemm_nt_bias<<<dim3(8, 64), 256>>>(kv,    v_w, v_b, Vb, NB * SK, DMODEL, DMODEL);

    // RoPE (q positions stride 2, k positions stride 1)
    rope_kernel<<<NB * SQ, 512>>>(Qb, SQ, 2);
    rope_kernel<<<NB * SK, 512>>>(Kb, SK, 1);

    // Attention
    cudaFuncSetAttribute(attn_kernel, cudaFuncAttributeMaxDynamicSharedMemorySize, ATTN_SMEM);
    attn_kernel<<<dim3(SQ / 64, NHEAD, NB), 256, ATTN_SMEM>>>(Qb, Kb, Vb, Ob);

    // Output projection
    gemm_nt_bias<<<dim3(8, 32), 256>>>(Ob, out_w, out_b, out, NB * SQ, DMODEL, DMODEL);
}

// round 3
// speedup vs baseline: 1.5018x; 1.5018x over previous
#include <cuda_runtime.h>
#include <cuda_bf16.h>
#include <math.h>
#include <stdint.h>

#define DMODEL 1024
#define NHEAD  16
#define HD     64
#define NB     4
#define SQ     1024
#define SK     2048

// ---------------------------------------------------------------------------
// Scratch (__device__ globals: allocation-free rule)
// ---------------------------------------------------------------------------
__device__ float g_Q[NB * SQ * DMODEL];
__device__ float g_K[NB * SK * DMODEL];
__device__ float g_V[NB * SK * DMODEL];
__device__ float g_O[NB * SQ * DMODEL];

__device__ __nv_bfloat16 g_qh[NB * SQ * DMODEL];
__device__ __nv_bfloat16 g_ql[NB * SQ * DMODEL];
__device__ __nv_bfloat16 g_kvh[NB * SK * DMODEL];
__device__ __nv_bfloat16 g_kvl[NB * SK * DMODEL];
__device__ __nv_bfloat16 g_oh[NB * SQ * DMODEL];
__device__ __nv_bfloat16 g_ol[NB * SQ * DMODEL];
__device__ __nv_bfloat16 g_wqh[DMODEL * DMODEL];
__device__ __nv_bfloat16 g_wql[DMODEL * DMODEL];
__device__ __nv_bfloat16 g_wkh[DMODEL * DMODEL];
__device__ __nv_bfloat16 g_wkl[DMODEL * DMODEL];
__device__ __nv_bfloat16 g_wvh[DMODEL * DMODEL];
__device__ __nv_bfloat16 g_wvl[DMODEL * DMODEL];
__device__ __nv_bfloat16 g_woh[DMODEL * DMODEL];
__device__ __nv_bfloat16 g_wol[DMODEL * DMODEL];

// ---------------------------------------------------------------------------
// Helpers (baseline PTX only: sm_80-level features, safe on compute_100)
// ---------------------------------------------------------------------------
__device__ __forceinline__ uint32_t smem_u32(const void* p) {
    uint32_t a;
    asm("{ .reg .u64 t; cvta.to.shared.u64 t, %1; cvt.u32.u64 %0, t; }" : "=r"(a) : "l"(p));
    return a;
}
__device__ __forceinline__ void cp16(uint32_t dst, const void* src) {
    asm volatile("cp.async.cg.shared.global [%0], [%1], 16;" :: "r"(dst), "l"(src));
}
__device__ __forceinline__ void cp_commit() {
    asm volatile("cp.async.commit_group;" ::: "memory");
}
__device__ __forceinline__ void cp_wait1() {
    asm volatile("cp.async.wait_group 1;" ::: "memory");
}
__device__ __forceinline__ void cp_wait0() {
    asm volatile("cp.async.wait_group 0;" ::: "memory");
}
__device__ __forceinline__ void ldsm_x4(uint32_t addr, uint32_t* r) {
    asm volatile("ldmatrix.sync.aligned.m8n8.x4.shared.b16 {%0,%1,%2,%3}, [%4];"
                 : "=r"(r[0]), "=r"(r[1]), "=r"(r[2]), "=r"(r[3]) : "r"(addr));
}
__device__ __forceinline__ void mma_bf16(float* d, const uint32_t* a, uint32_t b0, uint32_t b1) {
    asm volatile(
        "mma.sync.aligned.m16n8k16.row.col.f32.bf16.bf16.f32 "
        "{%0,%1,%2,%3}, {%4,%5,%6,%7}, {%8,%9}, {%0,%1,%2,%3};"
        : "+f"(d[0]), "+f"(d[1]), "+f"(d[2]), "+f"(d[3])
        : "r"(a[0]), "r"(a[1]), "r"(a[2]), "r"(a[3]), "r"(b0), "r"(b1));
}

// ---------------------------------------------------------------------------
// fp32 -> (bf16 hi, bf16 lo) split
// ---------------------------------------------------------------------------
__global__ void split_kernel(const float* __restrict__ x, __nv_bfloat16* __restrict__ hi,
                             __nv_bfloat16* __restrict__ lo, int n)
{
    int i = (blockIdx.x * blockDim.x + threadIdx.x) * 4;
    if (i >= n) return;
    float4 v = *(const float4*)(x + i);
    float f[4] = {v.x, v.y, v.z, v.w};
    uint32_t hs[4], ls[4];
#pragma unroll
    for (int c = 0; c < 4; c++) {
        __nv_bfloat16 hb = __float2bfloat16(f[c]);
        float r = f[c] - __bfloat162float(hb);
        __nv_bfloat16 lb = __float2bfloat16(r);
        hs[c] = (uint32_t)__bfloat16_as_ushort(hb);
        ls[c] = (uint32_t)__bfloat16_as_ushort(lb);
    }
    uint2 hv = make_uint2(hs[0] | (hs[1] << 16), hs[2] | (hs[3] << 16));
    uint2 lv = make_uint2(ls[0] | (ls[1] << 16), ls[2] | (ls[3] << 16));
    *(uint2*)(hi + i) = hv;
    *(uint2*)(lo + i) = lv;
}

// ---------------------------------------------------------------------------
// bf16-split GEMM via mma.sync:  C[M,1024] = A @ W^T + bias
//   C = Ahi*Whi^T + Alo*Whi^T + Ahi*Wlo^T  (fp32 accumulate)
// 128x128 CTA tile, BK=64 (128B rows, SW128 XOR swizzle), 8 warps (4m x 2n),
// warp tile 32x64, cp.async double buffer, ldmatrix.x4 fragments.
// ---------------------------------------------------------------------------
#define GEMM_SMEM 65536
#define NCHUNK 48

__global__ __launch_bounds__(256)
void mma_gemm(const __nv_bfloat16* __restrict__ Ahi, const __nv_bfloat16* __restrict__ Alo,
              const __nv_bfloat16* __restrict__ Whi, const __nv_bfloat16* __restrict__ Wlo,
              const float* __restrict__ bias, float* __restrict__ C)
{
    extern __shared__ char smc[];
    const uint32_t sbase = smem_u32(smc);
    const int tid = threadIdx.x;
    const int lane = tid & 31;
    const int wid = tid >> 5;
    const int warp_m = wid & 3;    // 4 warps along M (32 rows each)
    const int warp_n = wid >> 2;   // 2 warps along N (64 cols each)
    const int m0 = blockIdx.y * 128;
    const int n0 = blockIdx.x * 128;

    // smem: Abuf0 @0, Bbuf0 @16384, Abuf1 @32768, Bbuf1 @49152 (each 16KB)
    const int lc = tid & 7;    // 16B chunk within 128B row
    const int lr = tid >> 3;   // base row 0..31

    float acc[2][8][4];
#pragma unroll
    for (int mi = 0; mi < 2; mi++)
#pragma unroll
        for (int ni = 0; ni < 8; ni++)
#pragma unroll
            for (int e = 0; e < 4; e++) acc[mi][ni][e] = 0.f;

    // ---- async load of one K-chunk (64 bf16 = 128B per row) into buffer ----
    auto issue_load = [&](int ci) {
        const int seg = ci >> 4;
        const int kk = (ci & 15) << 6;
        const __nv_bfloat16* As = (seg == 1) ? Alo : Ahi;
        const __nv_bfloat16* Ws = (seg == 2) ? Wlo : Whi;
        const uint32_t aoff = (ci & 1) ? 32768u : 0u;
        const uint32_t da = sbase + aoff;
        const uint32_t db = sbase + aoff + 16384u;
        const uint32_t sw = ((uint32_t)(lc ^ (lr & 7))) << 4;  // (r&7) invariant under +32
#pragma unroll
        for (int p = 0; p < 4; p++) {
            const int r = lr + p * 32;
            const uint32_t so = (uint32_t)(r * 128) + sw;
            cp16(da + so, As + (size_t)(m0 + r) * DMODEL + kk + lc * 8);
            cp16(db + so, Ws + (size_t)(n0 + r) * DMODEL + kk + lc * 8);
        }
    };

    issue_load(0);
    cp_commit();

    for (int i = 0; i < NCHUNK; i++) {
        if (i + 1 < NCHUNK) {
            issue_load(i + 1);
            cp_commit();
            cp_wait1();
        } else {
            cp_wait0();
        }
        __syncthreads();

        const uint32_t aoff = (i & 1) ? 32768u : 0u;
        const uint32_t abase = sbase + aoff + (uint32_t)(warp_m * 32) * 128;
        const uint32_t bbase = sbase + aoff + 16384u + (uint32_t)(warp_n * 64) * 128;

#pragma unroll
        for (int ks = 0; ks < 4; ks++) {
            uint32_t afr[2][4];
#pragma unroll
            for (int mi = 0; mi < 2; mi++) {
                const int row = mi * 16 + (lane & 15);
                const int ch = ks * 2 + (lane >> 4);
                ldsm_x4(abase + (uint32_t)(row * 128) + (((uint32_t)(ch ^ (row & 7))) << 4),
                        afr[mi]);
            }
#pragma unroll
            for (int g = 0; g < 4; g++) {
                const int n = g * 16 + (lane & 7) + ((lane & 16) >> 1);
                const int ch = ks * 2 + ((lane >> 3) & 1);
                uint32_t bfr[4];
                ldsm_x4(bbase + (uint32_t)(n * 128) + (((uint32_t)(ch ^ (n & 7))) << 4), bfr);
#pragma unroll
                for (int mi = 0; mi < 2; mi++) {
                    mma_bf16(acc[mi][2 * g + 0], afr[mi], bfr[0], bfr[1]);
                    mma_bf16(acc[mi][2 * g + 1], afr[mi], bfr[2], bfr[3]);
                }
            }
        }
        __syncthreads();
    }

    // ---- epilogue: + bias, fp32 store ----
#pragma unroll
    for (int mi = 0; mi < 2; mi++) {
        const int row = m0 + warp_m * 32 + mi * 16 + (lane >> 2);
#pragma unroll
        for (int ni = 0; ni < 8; ni++) {
            const int col = n0 + warp_n * 64 + ni * 8 + (lane & 3) * 2;
            const float bx = bias[col], by = bias[col + 1];
            float2 lo = make_float2(acc[mi][ni][0] + bx, acc[mi][ni][1] + by);
            float2 hi = make_float2(acc[mi][ni][2] + bx, acc[mi][ni][3] + by);
            *(float2*)&C[(size_t)row * DMODEL + col] = lo;
            *(float2*)&C[(size_t)(row + 8) * DMODEL + col] = hi;
        }
    }
}

// ---------------------------------------------------------------------------
// RoPE (unchanged)
// ---------------------------------------------------------------------------
__global__ void rope_kernel(float* __restrict__ X, int L, int posStride)
{
    int row = blockIdx.x;
    int t = threadIdx.x;
    int h = t >> 5;
    int j = t & 31;
    float pos = (float)((row % L) * posStride);
    float inv = 1.0f / powf(10000.0f, (float)j * (1.0f / 32.0f));
    float ang = pos * inv;
    float s, c;
    sincosf(ang, &s, &c);
    float* p = X + (size_t)row * DMODEL + h * HD + j;
    float x1 = p[0];
    float x2 = p[32];
    p[0]  = x1 * c - x2 * s;
    p[32] = x2 * c + x1 * s;
}

// ---------------------------------------------------------------------------
// Flash attention (fp32 SIMT, unchanged from R1)
// ---------------------------------------------------------------------------
#define AST 65
#define ATTN_SMEM (4 * 64 * AST * 4)

__global__ __launch_bounds__(256)
void attn_kernel(const float* __restrict__ Q, const float* __restrict__ Km,
                 const float* __restrict__ Vm, float* __restrict__ Oo)
{
    extern __shared__ float sm[];
    float* Qt = sm;
    float* Kt = Qt + 64 * AST;
    float* Vs = Kt + 64 * AST;
    float* Ps = Vs + 64 * AST;

    const int tid = threadIdx.x;
    const int tx = tid & 15;
    const int ty = tid >> 4;
    const int s0 = blockIdx.x * 64;
    const int h  = blockIdx.y;
    const int b  = blockIdx.z;

    {
        const float* src = Q + (size_t)(b * SQ + s0) * DMODEL + h * HD;
#pragma unroll
        for (int u = 0; u < 4; u++) {
            int e = tid + u * 256;
            int r = e >> 4;
            int d4 = (e & 15) << 2;
            float4 v = *(const float4*)&src[r * DMODEL + d4];
            Qt[(d4 + 0) * AST + r] = v.x * 0.125f;
            Qt[(d4 + 1) * AST + r] = v.y * 0.125f;
            Qt[(d4 + 2) * AST + r] = v.z * 0.125f;
            Qt[(d4 + 3) * AST + r] = v.w * 0.125f;
        }
    }

    float m_i[4], l_i[4], oacc[4][4];
#pragma unroll
    for (int i = 0; i < 4; i++) {
        m_i[i] = -INFINITY;
        l_i[i] = 0.f;
#pragma unroll
        for (int j = 0; j < 4; j++) oacc[i][j] = 0.f;
    }

    const float* ksrc = Km + (size_t)(b * SK) * DMODEL + h * HD;
    const float* vsrc = Vm + (size_t)(b * SK) * DMODEL + h * HD;

    for (int c0 = 0; c0 < SK; c0 += 64) {
#pragma unroll
        for (int u = 0; u < 4; u++) {
            int e = tid + u * 256;
            int r = e >> 4;
            int d4 = (e & 15) << 2;
            float4 kv4 = *(const float4*)&ksrc[(c0 + r) * DMODEL + d4];
            Kt[(d4 + 0) * AST + r] = kv4.x;
            Kt[(d4 + 1) * AST + r] = kv4.y;
            Kt[(d4 + 2) * AST + r] = kv4.z;
            Kt[(d4 + 3) * AST + r] = kv4.w;
            float4 vv4 = *(const float4*)&vsrc[(c0 + r) * DMODEL + d4];
            Vs[r * AST + d4 + 0] = vv4.x;
            Vs[r * AST + d4 + 1] = vv4.y;
            Vs[r * AST + d4 + 2] = vv4.z;
            Vs[r * AST + d4 + 3] = vv4.w;
        }
        __syncthreads();

        float sc[4][4];
#pragma unroll
        for (int i = 0; i < 4; i++)
#pragma unroll
            for (int j = 0; j < 4; j++) sc[i][j] = 0.f;

#pragma unroll 4
        for (int d = 0; d < 64; d++) {
            float q0 = Qt[d * AST + ty * 4 + 0];
            float q1 = Qt[d * AST + ty * 4 + 1];
            float q2 = Qt[d * AST + ty * 4 + 2];
            float q3 = Qt[d * AST + ty * 4 + 3];
            float k0 = Kt[d * AST + tx * 4 + 0];
            float k1 = Kt[d * AST + tx * 4 + 1];
            float k2 = Kt[d * AST + tx * 4 + 2];
            float k3 = Kt[d * AST + tx * 4 + 3];
            sc[0][0] = fmaf(q0, k0, sc[0][0]); sc[0][1] = fmaf(q0, k1, sc[0][1]);
            sc[0][2] = fmaf(q0, k2, sc[0][2]); sc[0][3] = fmaf(q0, k3, sc[0][3]);
            sc[1][0] = fmaf(q1, k0, sc[1][0]); sc[1][1] = fmaf(q1, k1, sc[1][1]);
            sc[1][2] = fmaf(q1, k2, sc[1][2]); sc[1][3] = fmaf(q1, k3, sc[1][3]);
            sc[2][0] = fmaf(q2, k0, sc[2][0]); sc[2][1] = fmaf(q2, k1, sc[2][1]);
            sc[2][2] = fmaf(q2, k2, sc[2][2]); sc[2][3] = fmaf(q2, k3, sc[2][3]);
            sc[3][0] = fmaf(q3, k0, sc[3][0]); sc[3][1] = fmaf(q3, k1, sc[3][1]);
            sc[3][2] = fmaf(q3, k2, sc[3][2]); sc[3][3] = fmaf(q3, k3, sc[3][3]);
        }

#pragma unroll
        for (int i = 0; i < 4; i++) {
            float mx = fmaxf(fmaxf(sc[i][0], sc[i][1]), fmaxf(sc[i][2], sc[i][3]));
#pragma unroll
            for (int off = 8; off >= 1; off >>= 1)
                mx = fmaxf(mx, __shfl_xor_sync(0xffffffffu, mx, off));
            float mnew = fmaxf(m_i[i], mx);
            float ssum = 0.f;
#pragma unroll
            for (int j = 0; j < 4; j++) {
                float p = expf(sc[i][j] - mnew);
                sc[i][j] = p;
                ssum += p;
            }
#pragma unroll
            for (int off = 8; off >= 1; off >>= 1)
                ssum += __shfl_xor_sync(0xffffffffu, ssum, off);
            float alpha = expf(m_i[i] - mnew);
            l_i[i] = l_i[i] * alpha + ssum;
            m_i[i] = mnew;
#pragma unroll
            for (int j = 0; j < 4; j++) {
                oacc[i][j] *= alpha;
                Ps[(ty * 4 + i) * AST + tx * 4 + j] = sc[i][j];
            }
        }
        __syncthreads();

#pragma unroll 4
        for (int k = 0; k < 64; k++) {
            float p0 = Ps[(ty * 4 + 0) * AST + k];
            float p1 = Ps[(ty * 4 + 1) * AST + k];
            float p2 = Ps[(ty * 4 + 2) * AST + k];
            float p3 = Ps[(ty * 4 + 3) * AST + k];
#pragma unroll
            for (int j = 0; j < 4; j++) {
                float v = Vs[k * AST + tx * 4 + j];
                oacc[0][j] = fmaf(p0, v, oacc[0][j]);
                oacc[1][j] = fmaf(p1, v, oacc[1][j]);
                oacc[2][j] = fmaf(p2, v, oacc[2][j]);
                oacc[3][j] = fmaf(p3, v, oacc[3][j]);
            }
        }
        __syncthreads();
    }

#pragma unroll
    for (int i = 0; i < 4; i++) {
        float invl = 1.0f / l_i[i];
        int r = s0 + ty * 4 + i;
        float4 o4 = make_float4(oacc[i][0] * invl, oacc[i][1] * invl,
                                oacc[i][2] * invl, oacc[i][3] * invl);
        *(float4*)&Oo[(size_t)(b * SQ + r) * DMODEL + h * HD + tx * 4] = o4;
    }
}

// ---------------------------------------------------------------------------
extern "C" void kernel_launch(void* const* d_in, const int* in_sizes, int n_in,
                              void* d_out, int out_size)
{
    const float* query = (const float*)d_in[0];
    const float* kv    = (const float*)d_in[1];
    const float* q_w   = (const float*)d_in[2];
    const float* q_b   = (const float*)d_in[3];
    const float* k_w   = (const float*)d_in[4];
    const float* k_b   = (const float*)d_in[5];
    const float* v_w   = (const float*)d_in[6];
    const float* v_b   = (const float*)d_in[7];
    const float* out_w = (const float*)d_in[8];
    const float* out_b = (const float*)d_in[9];
    float* out = (float*)d_out;

    float *Qb, *Kb, *Vb, *Ob;
    cudaGetSymbolAddress((void**)&Qb, g_Q);
    cudaGetSymbolAddress((void**)&Kb, g_K);
    cudaGetSymbolAddress((void**)&Vb, g_V);
    cudaGetSymbolAddress((void**)&Ob, g_O);
    __nv_bfloat16 *qh, *ql, *kvh, *kvl, *oh, *ol;
    __nv_bfloat16 *wqh, *wql, *wkh, *wkl, *wvh, *wvl, *woh, *wol;
    cudaGetSymbolAddress((void**)&qh,  g_qh);  cudaGetSymbolAddress((void**)&ql,  g_ql);
    cudaGetSymbolAddress((void**)&kvh, g_kvh); cudaGetSymbolAddress((void**)&kvl, g_kvl);
    cudaGetSymbolAddress((void**)&oh,  g_oh);  cudaGetSymbolAddress((void**)&ol,  g_ol);
    cudaGetSymbolAddress((void**)&wqh, g_wqh); cudaGetSymbolAddress((void**)&wql, g_wql);
    cudaGetSymbolAddress((void**)&wkh, g_wkh); cudaGetSymbolAddress((void**)&wkl, g_wkl);
    cudaGetSymbolAddress((void**)&wvh, g_wvh); cudaGetSymbolAddress((void**)&wvl, g_wvl);
    cudaGetSymbolAddress((void**)&woh, g_woh); cudaGetSymbolAddress((void**)&wol, g_wol);

    const int NQ = NB * SQ * DMODEL;   // 4M
    const int NK = NB * SK * DMODEL;   // 8M
    const int NW = DMODEL * DMODEL;    // 1M

    // hi/lo splits
    split_kernel<<<NQ / 1024, 256>>>(query, qh, ql, NQ);
    split_kernel<<<NK / 1024, 256>>>(kv, kvh, kvl, NK);
    split_kernel<<<NW / 1024, 256>>>(q_w, wqh, wql, NW);
    split_kernel<<<NW / 1024, 256>>>(k_w, wkh, wkl, NW);
    split_kernel<<<NW / 1024, 256>>>(v_w, wvh, wvl, NW);
    split_kernel<<<NW / 1024, 256>>>(out_w, woh, wol, NW);

    // Projections via mma.sync (bf16 3-term)
    cudaFuncSetAttribute(mma_gemm, cudaFuncAttributeMaxDynamicSharedMemorySize, GEMM_SMEM);
    mma_gemm<<<dim3(8, 32), 256, GEMM_SMEM>>>(qh, ql, wqh, wql, q_b, Qb);
    mma_gemm<<<dim3(8, 64), 256, GEMM_SMEM>>>(kvh, kvl, wkh, wkl, k_b, Kb);
    mma_gemm<<<dim3(8, 64), 256, GEMM_SMEM>>>(kvh, kvl, wvh, wvl, v_b, Vb);

    // RoPE
    rope_kernel<<<NB * SQ, 512>>>(Qb, SQ, 2);
    rope_kernel<<<NB * SK, 512>>>(Kb, SK, 1);

    // Attention (fp32 flash)
    cudaFuncSetAttribute(attn_kernel, cudaFuncAttributeMaxDynamicSharedMemorySize, ATTN_SMEM);
    attn_kernel<<<dim3(SQ / 64, NHEAD, NB), 256, ATTN_SMEM>>>(Qb, Kb, Vb, Ob);

    // Output projection
    split_kernel<<<NQ / 1024, 256>>>(Ob, oh, ol, NQ);
    mma_gemm<<<dim3(8, 32), 256, GEMM_SMEM>>>(oh, ol, woh, wol, out_b, out);
}

// round 4
// speedup vs baseline: 2.9179x; 1.9430x over previous
#include <cuda_runtime.h>
#include <cuda_bf16.h>
#include <math.h>
#include <stdint.h>

#define DMODEL 1024
#define NHEAD  16
#define HD     64
#define NB     4
#define SQ     1024
#define SK     2048

// ---------------------------------------------------------------------------
// Scratch (__device__ globals: allocation-free rule)
// ---------------------------------------------------------------------------
__device__ float g_Q[NB * SQ * DMODEL];
__device__ float g_K[NB * SK * DMODEL];
__device__ float g_V[NB * SK * DMODEL];
__device__ float g_O[NB * SQ * DMODEL];

__device__ __nv_bfloat16 g_qh[NB * SQ * DMODEL];
__device__ __nv_bfloat16 g_ql[NB * SQ * DMODEL];
__device__ __nv_bfloat16 g_kvh[NB * SK * DMODEL];
__device__ __nv_bfloat16 g_kvl[NB * SK * DMODEL];
__device__ __nv_bfloat16 g_oh[NB * SQ * DMODEL];
__device__ __nv_bfloat16 g_ol[NB * SQ * DMODEL];
__device__ __nv_bfloat16 g_wqh[DMODEL * DMODEL];
__device__ __nv_bfloat16 g_wql[DMODEL * DMODEL];
__device__ __nv_bfloat16 g_wkh[DMODEL * DMODEL];
__device__ __nv_bfloat16 g_wkl[DMODEL * DMODEL];
__device__ __nv_bfloat16 g_wvh[DMODEL * DMODEL];
__device__ __nv_bfloat16 g_wvl[DMODEL * DMODEL];
__device__ __nv_bfloat16 g_woh[DMODEL * DMODEL];
__device__ __nv_bfloat16 g_wol[DMODEL * DMODEL];

// attention operands (bf16 hi/lo, post-RoPE)
__device__ __nv_bfloat16 g_aqh[NB * SQ * DMODEL];
__device__ __nv_bfloat16 g_aql[NB * SQ * DMODEL];
__device__ __nv_bfloat16 g_akh[NB * SK * DMODEL];
__device__ __nv_bfloat16 g_akl[NB * SK * DMODEL];
__device__ __nv_bfloat16 g_avh[NB * SK * DMODEL];
__device__ __nv_bfloat16 g_avl[NB * SK * DMODEL];

// ---------------------------------------------------------------------------
// Helpers (sm_80-level PTX only; validated on this toolchain in R3)
// ---------------------------------------------------------------------------
__device__ __forceinline__ uint32_t smem_u32(const void* p) {
    uint32_t a;
    asm("{ .reg .u64 t; cvta.to.shared.u64 t, %1; cvt.u32.u64 %0, t; }" : "=r"(a) : "l"(p));
    return a;
}
__device__ __forceinline__ void cp16(uint32_t dst, const void* src) {
    asm volatile("cp.async.cg.shared.global [%0], [%1], 16;" :: "r"(dst), "l"(src));
}
__device__ __forceinline__ void cp_commit() {
    asm volatile("cp.async.commit_group;" ::: "memory");
}
__device__ __forceinline__ void cp_wait1() {
    asm volatile("cp.async.wait_group 1;" ::: "memory");
}
__device__ __forceinline__ void cp_wait0() {
    asm volatile("cp.async.wait_group 0;" ::: "memory");
}
__device__ __forceinline__ void ldsm_x4(uint32_t addr, uint32_t* r) {
    asm volatile("ldmatrix.sync.aligned.m8n8.x4.shared.b16 {%0,%1,%2,%3}, [%4];"
                 : "=r"(r[0]), "=r"(r[1]), "=r"(r[2]), "=r"(r[3]) : "r"(addr));
}
__device__ __forceinline__ void ldsm_x4t(uint32_t addr, uint32_t* r) {
    asm volatile("ldmatrix.sync.aligned.m8n8.x4.trans.shared.b16 {%0,%1,%2,%3}, [%4];"
                 : "=r"(r[0]), "=r"(r[1]), "=r"(r[2]), "=r"(r[3]) : "r"(addr));
}
__device__ __forceinline__ void mma_bf16(float* d, const uint32_t* a, uint32_t b0, uint32_t b1) {
    asm volatile(
        "mma.sync.aligned.m16n8k16.row.col.f32.bf16.bf16.f32 "
        "{%0,%1,%2,%3}, {%4,%5,%6,%7}, {%8,%9}, {%0,%1,%2,%3};"
        : "+f"(d[0]), "+f"(d[1]), "+f"(d[2]), "+f"(d[3])
        : "r"(a[0]), "r"(a[1]), "r"(a[2]), "r"(a[3]), "r"(b0), "r"(b1));
}
// exp on the FMA pipe: 2^(x*log2e), deg-5 poly, exponent via int add. rel err ~5e-7.
__device__ __forceinline__ float fast_exp(float x) {
    float y = fmaxf(x * 1.4426950408889634f, -100.0f);
    int n = __float2int_rn(y);
    float f = y - (float)n;
    float p = 1.3333558146e-3f;
    p = fmaf(p, f, 9.6181291076e-3f);
    p = fmaf(p, f, 5.5504108665e-2f);
    p = fmaf(p, f, 2.4022650696e-1f);
    p = fmaf(p, f, 6.9314718056e-1f);
    p = fmaf(p, f, 1.0f);
    return __int_as_float(__float_as_int(p) + (n << 23));
}
// split (a,b) fp32 pair -> bf16x2 hi + bf16x2 lo (lo = residual)
__device__ __forceinline__ void pack_split(float a, float b, uint32_t& hi2, uint32_t& lo2) {
    __nv_bfloat162 hb = __float22bfloat162_rn(make_float2(a, b));  // .x=a(low), .y=b(high)
    uint32_t h;
    memcpy(&h, &hb, 4);
    float ra = a - __uint_as_float(h << 16);
    float rb = b - __uint_as_float(h & 0xFFFF0000u);
    __nv_bfloat162 lb = __float22bfloat162_rn(make_float2(ra, rb));
    uint32_t l;
    memcpy(&l, &lb, 4);
    hi2 = h; lo2 = l;
}

// ---------------------------------------------------------------------------
// fp32 -> (bf16 hi, bf16 lo) split
// ---------------------------------------------------------------------------
__global__ void split_kernel(const float* __restrict__ x, __nv_bfloat16* __restrict__ hi,
                             __nv_bfloat16* __restrict__ lo, int n)
{
    int i = (blockIdx.x * blockDim.x + threadIdx.x) * 4;
    if (i >= n) return;
    float4 v = *(const float4*)(x + i);
    float f[4] = {v.x, v.y, v.z, v.w};
    uint32_t hs[4], ls[4];
#pragma unroll
    for (int c = 0; c < 4; c++) {
        __nv_bfloat16 hb = __float2bfloat16(f[c]);
        float r = f[c] - __bfloat162float(hb);
        __nv_bfloat16 lb = __float2bfloat16(r);
        hs[c] = (uint32_t)__bfloat16_as_ushort(hb);
        ls[c] = (uint32_t)__bfloat16_as_ushort(lb);
    }
    uint2 hv = make_uint2(hs[0] | (hs[1] << 16), hs[2] | (hs[3] << 16));
    uint2 lv = make_uint2(ls[0] | (ls[1] << 16), ls[2] | (ls[3] << 16));
    *(uint2*)(hi + i) = hv;
    *(uint2*)(lo + i) = lv;
}

// ---------------------------------------------------------------------------
// RoPE + bf16 hi/lo split (scale folded in for Q)
// ---------------------------------------------------------------------------
__global__ void rope_split(const float* __restrict__ X, __nv_bfloat16* __restrict__ hi,
                           __nv_bfloat16* __restrict__ lo, int L, int posStride, float scale)
{
    int row = blockIdx.x;
    int t = threadIdx.x;
    int h = t >> 5;
    int j = t & 31;
    float pos = (float)((row % L) * posStride);
    float inv = 1.0f / powf(10000.0f, (float)j * (1.0f / 32.0f));
    float s, c;
    sincosf(pos * inv, &s, &c);
    const float* p = X + (size_t)row * DMODEL + h * HD + j;
    float x1 = p[0];
    float x2 = p[32];
    float y1 = (x1 * c - x2 * s) * scale;
    float y2 = (x2 * c + x1 * s) * scale;
    size_t idx = (size_t)row * DMODEL + h * HD + j;
    __nv_bfloat16 h1 = __float2bfloat16(y1);
    __nv_bfloat16 h2 = __float2bfloat16(y2);
    hi[idx]      = h1;
    hi[idx + 32] = h2;
    lo[idx]      = __float2bfloat16(y1 - __bfloat162float(h1));
    lo[idx + 32] = __float2bfloat16(y2 - __bfloat162float(h2));
}

// ---------------------------------------------------------------------------
// bf16-split GEMM via mma.sync (unchanged, validated in R3)
// ---------------------------------------------------------------------------
#define GEMM_SMEM 65536
#define NCHUNK 48

__global__ __launch_bounds__(256)
void mma_gemm(const __nv_bfloat16* __restrict__ Ahi, const __nv_bfloat16* __restrict__ Alo,
              const __nv_bfloat16* __restrict__ Whi, const __nv_bfloat16* __restrict__ Wlo,
              const float* __restrict__ bias, float* __restrict__ C)
{
    extern __shared__ char smc[];
    const uint32_t sbase = smem_u32(smc);
    const int tid = threadIdx.x;
    const int lane = tid & 31;
    const int wid = tid >> 5;
    const int warp_m = wid & 3;
    const int warp_n = wid >> 2;
    const int m0 = blockIdx.y * 128;
    const int n0 = blockIdx.x * 128;

    const int lc = tid & 7;
    const int lr = tid >> 3;

    float acc[2][8][4];
#pragma unroll
    for (int mi = 0; mi < 2; mi++)
#pragma unroll
        for (int ni = 0; ni < 8; ni++)
#pragma unroll
            for (int e = 0; e < 4; e++) acc[mi][ni][e] = 0.f;

    auto issue_load = [&](int ci) {
        const int seg = ci >> 4;
        const int kk = (ci & 15) << 6;
        const __nv_bfloat16* As = (seg == 1) ? Alo : Ahi;
        const __nv_bfloat16* Ws = (seg == 2) ? Wlo : Whi;
        const uint32_t aoff = (ci & 1) ? 32768u : 0u;
        const uint32_t da = sbase + aoff;
        const uint32_t db = sbase + aoff + 16384u;
        const uint32_t sw = ((uint32_t)(lc ^ (lr & 7))) << 4;
#pragma unroll
        for (int p = 0; p < 4; p++) {
            const int r = lr + p * 32;
            const uint32_t so = (uint32_t)(r * 128) + sw;
            cp16(da + so, As + (size_t)(m0 + r) * DMODEL + kk + lc * 8);
            cp16(db + so, Ws + (size_t)(n0 + r) * DMODEL + kk + lc * 8);
        }
    };

    issue_load(0);
    cp_commit();

    for (int i = 0; i < NCHUNK; i++) {
        if (i + 1 < NCHUNK) {
            issue_load(i + 1);
            cp_commit();
            cp_wait1();
        } else {
            cp_wait0();
        }
        __syncthreads();

        const uint32_t aoff = (i & 1) ? 32768u : 0u;
        const uint32_t abase = sbase + aoff + (uint32_t)(warp_m * 32) * 128;
        const uint32_t bbase = sbase + aoff + 16384u + (uint32_t)(warp_n * 64) * 128;

#pragma unroll
        for (int ks = 0; ks < 4; ks++) {
            uint32_t afr[2][4];
#pragma unroll
            for (int mi = 0; mi < 2; mi++) {
                const int row = mi * 16 + (lane & 15);
                const int ch = ks * 2 + (lane >> 4);
                ldsm_x4(abase + (uint32_t)(row * 128) + (((uint32_t)(ch ^ (row & 7))) << 4),
                        afr[mi]);
            }
#pragma unroll
            for (int g = 0; g < 4; g++) {
                const int n = g * 16 + (lane & 7) + ((lane & 16) >> 1);
                const int ch = ks * 2 + ((lane >> 3) & 1);
                uint32_t bfr[4];
                ldsm_x4(bbase + (uint32_t)(n * 128) + (((uint32_t)(ch ^ (n & 7))) << 4), bfr);
#pragma unroll
                for (int mi = 0; mi < 2; mi++) {
                    mma_bf16(acc[mi][2 * g + 0], afr[mi], bfr[0], bfr[1]);
                    mma_bf16(acc[mi][2 * g + 1], afr[mi], bfr[2], bfr[3]);
                }
            }
        }
        __syncthreads();
    }

#pragma unroll
    for (int mi = 0; mi < 2; mi++) {
        const int row = m0 + warp_m * 32 + mi * 16 + (lane >> 2);
#pragma unroll
        for (int ni = 0; ni < 8; ni++) {
            const int col = n0 + warp_n * 64 + ni * 8 + (lane & 3) * 2;
            const float bx = bias[col], by = bias[col + 1];
            float2 lo = make_float2(acc[mi][ni][0] + bx, acc[mi][ni][1] + by);
            float2 hi = make_float2(acc[mi][ni][2] + bx, acc[mi][ni][3] + by);
            *(float2*)&C[(size_t)row * DMODEL + col] = lo;
            *(float2*)&C[(size_t)(row + 8) * DMODEL + col] = hi;
        }
    }
}

// ---------------------------------------------------------------------------
// Tensor-core flash attention (bf16 hi/lo 3-term for S and PV)
// Block: 128 queries x one (b,h). 8 warps, each owns 16 query rows.
// K/V consumed in 64-key chunks, cp.async double-buffered.
// ---------------------------------------------------------------------------
#define ATTN_SMEM 98304
#define NKCH (SK / 64)

__global__ __launch_bounds__(256, 1)
void attn_mma(const __nv_bfloat16* __restrict__ Qh, const __nv_bfloat16* __restrict__ Ql,
              const __nv_bfloat16* __restrict__ Kh, const __nv_bfloat16* __restrict__ Kl,
              const __nv_bfloat16* __restrict__ Vh, const __nv_bfloat16* __restrict__ Vl,
              float* __restrict__ O)
{
    extern __shared__ char smc[];
    const uint32_t sbase = smem_u32(smc);
    const int tid = threadIdx.x;
    const int lane = tid & 31;
    const int wid = tid >> 5;
    const int b = blockIdx.z;
    const int h = blockIdx.y;
    const int s0 = blockIdx.x * 128;

    // smem byte offsets
    const uint32_t QHS = 0, QLS = 16384, KHS = 32768, KLS = 49152, VHS = 65536, VLS = 81920;

    // ---- Q tile load (once): 128 rows x 128B, swizzled ----
    {
        const int r = tid >> 1;
        const int cb = (tid & 1) * 4;
        const size_t src = ((size_t)(b * SQ + s0 + r)) * DMODEL + h * HD;
#pragma unroll
        for (int u = 0; u < 4; u++) {
            const int c = cb + u;
            const uint32_t off = (uint32_t)(r * 128) + (((uint32_t)(c ^ (r & 7))) << 4);
            cp16(sbase + QHS + off, Qh + src + c * 8);
            cp16(sbase + QLS + off, Ql + src + c * 8);
        }
    }

    // ---- K/V chunk loader: 4 arrays x 8KB per chunk ----
    auto issue_kv = [&](int ci) {
        const uint32_t bo = (uint32_t)(ci & 1) * 8192u;
        const int r = tid >> 2;
        const int cb = (tid & 3) * 2;
        const size_t src = ((size_t)(b * SK + ci * 64 + r)) * DMODEL + h * HD;
#pragma unroll
        for (int u = 0; u < 2; u++) {
            const int c = cb + u;
            const uint32_t off = (uint32_t)(r * 128) + (((uint32_t)(c ^ (r & 7))) << 4);
            cp16(sbase + KHS + bo + off, Kh + src + c * 8);
            cp16(sbase + KLS + bo + off, Kl + src + c * 8);
            cp16(sbase + VHS + bo + off, Vh + src + c * 8);
            cp16(sbase + VLS + bo + off, Vl + src + c * 8);
        }
    };

    issue_kv(0);
    cp_commit();

    uint32_t qfh[4][4], qfl[4][4];
    float oacc[8][4];
#pragma unroll
    for (int g = 0; g < 8; g++)
#pragma unroll
        for (int e = 0; e < 4; e++) oacc[g][e] = 0.f;
    float m0 = -INFINITY, m1 = -INFINITY, l0 = 0.f, l1 = 0.f;

    for (int i = 0; i < NKCH; i++) {
        if (i + 1 < NKCH) {
            issue_kv(i + 1);
            cp_commit();
            cp_wait1();
        } else {
            cp_wait0();
        }
        __syncthreads();

        if (i == 0) {
            // Q fragments for this warp's 16 rows (reused all chunks)
            const int row = wid * 16 + (lane & 15);
#pragma unroll
            for (int ks = 0; ks < 4; ks++) {
                const int ch = ks * 2 + (lane >> 4);
                const uint32_t off = (uint32_t)(row * 128) + (((uint32_t)(ch ^ (row & 7))) << 4);
                ldsm_x4(sbase + QHS + off, qfh[ks]);
                ldsm_x4(sbase + QLS + off, qfl[ks]);
            }
        }

        const uint32_t bo = (uint32_t)(i & 1) * 8192u;
        const uint32_t kh = sbase + KHS + bo, kl = sbase + KLS + bo;
        const uint32_t vh = sbase + VHS + bo, vl = sbase + VLS + bo;

        // ---- S = Q K^T (3-term) ----
        float sacc[8][4];
#pragma unroll
        for (int g = 0; g < 8; g++)
#pragma unroll
            for (int e = 0; e < 4; e++) sacc[g][e] = 0.f;

#pragma unroll
        for (int ks = 0; ks < 4; ks++) {
#pragma unroll
            for (int g = 0; g < 4; g++) {
                const int n = g * 16 + (lane & 7) + ((lane & 16) >> 1);
                const int ch = ks * 2 + ((lane >> 3) & 1);
                const uint32_t off = (uint32_t)(n * 128) + (((uint32_t)(ch ^ (n & 7))) << 4);
                uint32_t bh[4], bl[4];
                ldsm_x4(kh + off, bh);
                ldsm_x4(kl + off, bl);
                mma_bf16(sacc[2 * g + 0], qfh[ks], bh[0], bh[1]);
                mma_bf16(sacc[2 * g + 0], qfl[ks], bh[0], bh[1]);
                mma_bf16(sacc[2 * g + 0], qfh[ks], bl[0], bl[1]);
                mma_bf16(sacc[2 * g + 1], qfh[ks], bh[2], bh[3]);
                mma_bf16(sacc[2 * g + 1], qfl[ks], bh[2], bh[3]);
                mma_bf16(sacc[2 * g + 1], qfh[ks], bl[2], bl[3]);
            }
        }

        // ---- online softmax (rows r0=lane>>2 and r0+8; cols spread over quad) ----
        float mx0 = sacc[0][0], mx1 = sacc[0][2];
#pragma unroll
        for (int g = 0; g < 8; g++) {
            mx0 = fmaxf(mx0, fmaxf(sacc[g][0], sacc[g][1]));
            mx1 = fmaxf(mx1, fmaxf(sacc[g][2], sacc[g][3]));
        }
        mx0 = fmaxf(mx0, __shfl_xor_sync(0xffffffffu, mx0, 1));
        mx0 = fmaxf(mx0, __shfl_xor_sync(0xffffffffu, mx0, 2));
        mx1 = fmaxf(mx1, __shfl_xor_sync(0xffffffffu, mx1, 1));
        mx1 = fmaxf(mx1, __shfl_xor_sync(0xffffffffu, mx1, 2));
        const float mn0 = fmaxf(m0, mx0);
        const float mn1 = fmaxf(m1, mx1);
        const float a0 = fast_exp(m0 - mn0);
        const float a1 = fast_exp(m1 - mn1);
        m0 = mn0; m1 = mn1;
        float s0s = 0.f, s1s = 0.f;
#pragma unroll
        for (int g = 0; g < 8; g++) {
            sacc[g][0] = fast_exp(sacc[g][0] - mn0);
            sacc[g][1] = fast_exp(sacc[g][1] - mn0);
            sacc[g][2] = fast_exp(sacc[g][2] - mn1);
            sacc[g][3] = fast_exp(sacc[g][3] - mn1);
            s0s += sacc[g][0] + sacc[g][1];
            s1s += sacc[g][2] + sacc[g][3];
        }
        l0 = l0 * a0 + s0s;   // lane-partial; quad-reduced at the end
        l1 = l1 * a1 + s1s;
#pragma unroll
        for (int g = 0; g < 8; g++) {
            oacc[g][0] *= a0; oacc[g][1] *= a0;
            oacc[g][2] *= a1; oacc[g][3] *= a1;
        }

        // ---- O += P V (3-term); P A-frag direct from C-frag layout ----
#pragma unroll
        for (int ks = 0; ks < 4; ks++) {
            uint32_t ah[4], al[4];
            pack_split(sacc[2 * ks][0],     sacc[2 * ks][1],     ah[0], al[0]);
            pack_split(sacc[2 * ks][2],     sacc[2 * ks][3],     ah[1], al[1]);
            pack_split(sacc[2 * ks + 1][0], sacc[2 * ks + 1][1], ah[2], al[2]);
            pack_split(sacc[2 * ks + 1][2], sacc[2 * ks + 1][3], ah[3], al[3]);
            const int tile2 = lane >> 3;
            const int key = ks * 16 + (tile2 & 1) * 8 + (lane & 7);
#pragma unroll
            for (int g = 0; g < 4; g++) {
                const int c = g * 2 + (tile2 >> 1);
                const uint32_t off = (uint32_t)(key * 128) + (((uint32_t)(c ^ (key & 7))) << 4);
                uint32_t bh[4], bl[4];
                ldsm_x4t(vh + off, bh);
                ldsm_x4t(vl + off, bl);
                mma_bf16(oacc[2 * g + 0], ah, bh[0], bh[1]);
                mma_bf16(oacc[2 * g + 0], al, bh[0], bh[1]);
                mma_bf16(oacc[2 * g + 0], ah, bl[0], bl[1]);
                mma_bf16(oacc[2 * g + 1], ah, bh[2], bh[3]);
                mma_bf16(oacc[2 * g + 1], al, bh[2], bh[3]);
                mma_bf16(oacc[2 * g + 1], ah, bl[2], bl[3]);
            }
        }
        __syncthreads();
    }

    // ---- finalize: quad-reduce l, normalize, store ----
    l0 += __shfl_xor_sync(0xffffffffu, l0, 1);
    l0 += __shfl_xor_sync(0xffffffffu, l0, 2);
    l1 += __shfl_xor_sync(0xffffffffu, l1, 1);
    l1 += __shfl_xor_sync(0xffffffffu, l1, 2);
    const float inv0 = 1.0f / l0;
    const float inv1 = 1.0f / l1;
    const int r0 = s0 + wid * 16 + (lane >> 2);
#pragma unroll
    for (int g = 0; g < 8; g++) {
        const int col = h * HD + g * 8 + (lane & 3) * 2;
        *(float2*)&O[((size_t)(b * SQ) + r0) * DMODEL + col] =
            make_float2(oacc[g][0] * inv0, oacc[g][1] * inv0);
        *(float2*)&O[((size_t)(b * SQ) + r0 + 8) * DMODEL + col] =
            make_float2(oacc[g][2] * inv1, oacc[g][3] * inv1);
    }
}

// ---------------------------------------------------------------------------
extern "C" void kernel_launch(void* const* d_in, const int* in_sizes, int n_in,
                              void* d_out, int out_size)
{
    const float* query = (const float*)d_in[0];
    const float* kv    = (const float*)d_in[1];
    const float* q_w   = (const float*)d_in[2];
    const float* q_b   = (const float*)d_in[3];
    const float* k_w   = (const float*)d_in[4];
    const float* k_b   = (const float*)d_in[5];
    const float* v_w   = (const float*)d_in[6];
    const float* v_b   = (const float*)d_in[7];
    const float* out_w = (const float*)d_in[8];
    const float* out_b = (const float*)d_in[9];
    float* out = (float*)d_out;

    float *Qb, *Kb, *Vb, *Ob;
    cudaGetSymbolAddress((void**)&Qb, g_Q);
    cudaGetSymbolAddress((void**)&Kb, g_K);
    cudaGetSymbolAddress((void**)&Vb, g_V);
    cudaGetSymbolAddress((void**)&Ob, g_O);
    __nv_bfloat16 *qh, *ql, *kvh, *kvl, *oh, *ol;
    __nv_bfloat16 *wqh, *wql, *wkh, *wkl, *wvh, *wvl, *woh, *wol;
    __nv_bfloat16 *aqh, *aql, *akh, *akl, *avh, *avl;
    cudaGetSymbolAddress((void**)&qh,  g_qh);  cudaGetSymbolAddress((void**)&ql,  g_ql);
    cudaGetSymbolAddress((void**)&kvh, g_kvh); cudaGetSymbolAddress((void**)&kvl, g_kvl);
    cudaGetSymbolAddress((void**)&oh,  g_oh);  cudaGetSymbolAddress((void**)&ol,  g_ol);
    cudaGetSymbolAddress((void**)&wqh, g_wqh); cudaGetSymbolAddress((void**)&wql, g_wql);
    cudaGetSymbolAddress((void**)&wkh, g_wkh); cudaGetSymbolAddress((void**)&wkl, g_wkl);
    cudaGetSymbolAddress((void**)&wvh, g_wvh); cudaGetSymbolAddress((void**)&wvl, g_wvl);
    cudaGetSymbolAddress((void**)&woh, g_woh); cudaGetSymbolAddress((void**)&wol, g_wol);
    cudaGetSymbolAddress((void**)&aqh, g_aqh); cudaGetSymbolAddress((void**)&aql, g_aql);
    cudaGetSymbolAddress((void**)&akh, g_akh); cudaGetSymbolAddress((void**)&akl, g_akl);
    cudaGetSymbolAddress((void**)&avh, g_avh); cudaGetSymbolAddress((void**)&avl, g_avl);

    const int NQ = NB * SQ * DMODEL;
    const int NK = NB * SK * DMODEL;
    const int NW = DMODEL * DMODEL;

    // input hi/lo splits
    split_kernel<<<NQ / 1024, 256>>>(query, qh, ql, NQ);
    split_kernel<<<NK / 1024, 256>>>(kv, kvh, kvl, NK);
    split_kernel<<<NW / 1024, 256>>>(q_w, wqh, wql, NW);
    split_kernel<<<NW / 1024, 256>>>(k_w, wkh, wkl, NW);
    split_kernel<<<NW / 1024, 256>>>(v_w, wvh, wvl, NW);
    split_kernel<<<NW / 1024, 256>>>(out_w, woh, wol, NW);

    // projections (fp32 out)
    cudaFuncSetAttribute(mma_gemm, cudaFuncAttributeMaxDynamicSharedMemorySize, GEMM_SMEM);
    mma_gemm<<<dim3(8, 32), 256, GEMM_SMEM>>>(qh, ql, wqh, wql, q_b, Qb);
    mma_gemm<<<dim3(8, 64), 256, GEMM_SMEM>>>(kvh, kvl, wkh, wkl, k_b, Kb);
    mma_gemm<<<dim3(8, 64), 256, GEMM_SMEM>>>(kvh, kvl, wvh, wvl, v_b, Vb);

    // RoPE + split to bf16 hi/lo (Q gets softmax scale 1/8 folded in)
    rope_split<<<NB * SQ, 512>>>(Qb, aqh, aql, SQ, 2, 0.125f);
    rope_split<<<NB * SK, 512>>>(Kb, akh, akl, SK, 1, 1.0f);
    split_kernel<<<NK / 1024, 256>>>(Vb, avh, avl, NK);

    // tensor-core flash attention
    cudaFuncSetAttribute(attn_mma, cudaFuncAttributeMaxDynamicSharedMemorySize, ATTN_SMEM);
    attn_mma<<<dim3(SQ / 128, NHEAD, NB), 256, ATTN_SMEM>>>(aqh, aql, akh, akl, avh, avl, Ob);

    // output projection
    split_kernel<<<NQ / 1024, 256>>>(Ob, oh, ol, NQ);
    mma_gemm<<<dim3(8, 32), 256, GEMM_SMEM>>>(oh, ol, woh, wol, out_b, out);
}